// round 3
// baseline (speedup 1.0000x reference)
#include <cuda_runtime.h>

#define N_ATOMS 512
#define FDIM    128
#define NKER    301
#define NLAYER  3
#define H_STEP  0.05f
#define INV_H   20.0f
#define NG      352
#define LN2     0.69314718056f
#define SPAD    132
#define CTHREADS 256

// ---- persistent device scratch (no runtime allocation) ----
__device__ float g_D[N_ATOMS * N_ATOMS];          // pairwise distances
__device__ float g_TAB[NLAYER * NG * FDIM];       // per-layer RBF@W1 table
__device__ float g_H[N_ATOMS * FDIM];             // node features
__device__ float g_O[N_ATOMS * FDIM];             // atomwise output
__device__ float g_CP[N_ATOMS * FDIM];            // conv output (pre-norm)

__device__ __forceinline__ float sspf(float v) {
    // softplus(v) - ln2, numerically stable
    float e = __expf(-fabsf(v));
    return fmaxf(v, 0.0f) + __logf(1.0f + e) - LN2;
}

// ---------------------------------------------------------------------------
// pairwise distances d[i][j] = |r_i - r_j|  (diagonal exactly 0)
// ---------------------------------------------------------------------------
__global__ void dist_kernel(const float* __restrict__ r) {
    int i = blockIdx.x;
    float rx = r[i * 3 + 0], ry = r[i * 3 + 1], rz = r[i * 3 + 2];
    for (int j = threadIdx.x; j < N_ATOMS; j += blockDim.x) {
        float dx = rx - r[j * 3 + 0];
        float dy = ry - r[j * 3 + 1];
        float dz = rz - r[j * 3 + 2];
        float d2 = dx * dx + dy * dy + dz * dz;
        g_D[i * N_ATOMS + j] = sqrtf(d2);
    }
}

// ---------------------------------------------------------------------------
// table: TAB[l][g][f] = sum_k exp(-10*(t_g - 0.1k)^2) * cf_W1[l][k][f]
// grid sample t_g = (g-1)*H_STEP, g in [0, NG)
// ---------------------------------------------------------------------------
__global__ void table_kernel(const float* __restrict__ cf_W1) {
    int g = blockIdx.x;
    int l = blockIdx.y;
    float t = (g - 1) * H_STEP;
    __shared__ float e_sm[NKER];
    for (int k = threadIdx.x; k < NKER; k += blockDim.x) {
        float u = t - 0.1f * (float)k;
        e_sm[k] = expf(-10.0f * u * u);
    }
    __syncthreads();
    int f = threadIdx.x;
    const float* W = cf_W1 + l * NKER * FDIM + f;
    float acc = 0.0f;
    for (int k = 0; k < NKER; k++)
        acc = fmaf(e_sm[k], W[k * FDIM], acc);
    g_TAB[(l * NG + g) * FDIM + f] = acc;
}

// ---------------------------------------------------------------------------
__global__ void embed_kernel(const int* __restrict__ x, const float* __restrict__ emb) {
    int i = blockIdx.x;
    int f = threadIdx.x;
    g_H[i * FDIM + f] = emb[x[i] * FDIM + f];
}

// o = h @ W + b  (linear)
__global__ void atomwise_kernel(const float* __restrict__ W, const float* __restrict__ b) {
    int i = blockIdx.x, f = threadIdx.x;
    __shared__ float hrow[FDIM];
    hrow[f] = g_H[i * FDIM + f];
    __syncthreads();
    float acc = b[f];
#pragma unroll 8
    for (int k = 0; k < FDIM; k++) acc = fmaf(hrow[k], W[k * FDIM + f], acc);
    g_O[i * FDIM + f] = acc;
}

// ---------------------------------------------------------------------------
// conv: cpre[i,f] = sum_j o[j,f] * ssp( ssp(tab(d_ij)+b1) @ W2 + b2 )[f]
// one CTA per i; 4 j-tiles of 128 pairs; fused S-gen -> GEMM -> epilogue
// ---------------------------------------------------------------------------
__global__ void __launch_bounds__(CTHREADS, 2)
conv_kernel(int l, const float* __restrict__ W2,
            const float* __restrict__ b1, const float* __restrict__ b2)
{
    extern __shared__ float sm[];
    float* St  = sm;                   // [FDIM][SPAD]  S transposed: St[k=f][p=pair]
    float* red = St + FDIM * SPAD;     // [16][FDIM]
    float* b1s = red + 16 * FDIM;      // [FDIM]
    float* b2s = b1s + FDIM;           // [FDIM]
    float* dsm = b2s + FDIM;           // [128]

    const int i    = blockIdx.x;
    const int tid  = threadIdx.x;
    const int tr   = tid >> 4;         // 0..15 (row group of 8 pairs)
    const int tc   = tid & 15;         // 0..15 (col group of 8 feats)
    const int wrp  = tid >> 5;
    const int lane = tid & 31;

    if (tid < FDIM) { b1s[tid] = b1[tid]; b2s[tid] = b2[tid]; }

    const float* tab  = g_TAB + l * NG * FDIM;
    const float* Drow = g_D + i * N_ATOMS;

    float cacc[8];
#pragma unroll
    for (int c = 0; c < 8; c++) cacc[c] = 0.0f;

    for (int jt = 0; jt < 4; jt++) {
        __syncthreads();                       // St / dsm safe to overwrite
        if (tid < 128) dsm[tid] = Drow[jt * 128 + tid];
        __syncthreads();

        // ---- generate S tile: St[f][p] = ssp(catmull_rom(tab, d_p)[f] + b1[f])
        for (int p = wrp; p < 128; p += 8) {
            float d   = dsm[p];
            float a   = fminf(d * INV_H, 347.5f);
            float j0f = floorf(a);
            float x   = a - j0f;
            int   gi  = (int)j0f;
            float x2 = x * x, x3 = x2 * x;
            float cw0 = 0.5f * (-x3 + 2.0f * x2 - x);
            float cw1 = 0.5f * (3.0f * x3 - 5.0f * x2 + 2.0f);
            float cw2 = 0.5f * (-3.0f * x3 + 4.0f * x2 + x);
            float cw3 = 0.5f * (x3 - x2);
            const float* T = tab + gi * FDIM;
#pragma unroll
            for (int c = 0; c < 4; c++) {
                int f = lane + 32 * c;
                float u = cw0 * T[f]
                        + cw1 * T[FDIM + f]
                        + cw2 * T[2 * FDIM + f]
                        + cw3 * T[3 * FDIM + f];
                St[f * SPAD + p] = sspf(u + b1s[f]);
            }
        }
        __syncthreads();

        // ---- register-blocked GEMM: C[p,f'] = sum_k St[k][p] * W2[k][f']
        float C[8][8];
#pragma unroll
        for (int a_ = 0; a_ < 8; a_++)
#pragma unroll
            for (int c_ = 0; c_ < 8; c_++) C[a_][c_] = 0.0f;

        const float* Bp = W2 + tc * 8;
#pragma unroll 4
        for (int k = 0; k < FDIM; k++) {
            float4 a0  = *(const float4*)(St + k * SPAD + tr * 8);
            float4 a1  = *(const float4*)(St + k * SPAD + tr * 8 + 4);
            float4 bv0 = *(const float4*)(Bp + k * FDIM);
            float4 bv1 = *(const float4*)(Bp + k * FDIM + 4);
            float av[8] = {a0.x, a0.y, a0.z, a0.w, a1.x, a1.y, a1.z, a1.w};
            float bv[8] = {bv0.x, bv0.y, bv0.z, bv0.w, bv1.x, bv1.y, bv1.z, bv1.w};
#pragma unroll
            for (int r_ = 0; r_ < 8; r_++)
#pragma unroll
                for (int c_ = 0; c_ < 8; c_++)
                    C[r_][c_] = fmaf(av[r_], bv[c_], C[r_][c_]);
        }

        // ---- epilogue: ssp(C + b2) * o[j,f], accumulate over pair rows
#pragma unroll
        for (int r_ = 0; r_ < 8; r_++) {
            int j = jt * 128 + tr * 8 + r_;
            float4 o0 = *(const float4*)(g_O + j * FDIM + tc * 8);
            float4 o1 = *(const float4*)(g_O + j * FDIM + tc * 8 + 4);
            float ov[8] = {o0.x, o0.y, o0.z, o0.w, o1.x, o1.y, o1.z, o1.w};
#pragma unroll
            for (int c_ = 0; c_ < 8; c_++) {
                float wv = sspf(C[r_][c_] + b2s[tc * 8 + c_]);
                cacc[c_] = fmaf(ov[c_], wv, cacc[c_]);
            }
        }
    }

    // ---- cross-thread reduction over the 16 row-groups
    __syncthreads();
#pragma unroll
    for (int c_ = 0; c_ < 8; c_++) red[tr * FDIM + tc * 8 + c_] = cacc[c_];
    __syncthreads();
    if (tid < FDIM) {
        float s = 0.0f;
#pragma unroll
        for (int t = 0; t < 16; t++) s += red[t * FDIM + tid];
        g_CP[i * FDIM + tid] = s;
    }
}

// h += ssp(cpre @ n_W1 + n_b1) @ n_W2 + n_b2
__global__ void norm_kernel(const float* __restrict__ W1, const float* __restrict__ b1,
                            const float* __restrict__ W2, const float* __restrict__ b2) {
    int i = blockIdx.x, f = threadIdx.x;
    __shared__ float crow[FDIM];
    __shared__ float trow[FDIM];
    crow[f] = g_CP[i * FDIM + f];
    __syncthreads();
    float acc = b1[f];
#pragma unroll 8
    for (int k = 0; k < FDIM; k++) acc = fmaf(crow[k], W1[k * FDIM + f], acc);
    trow[f] = sspf(acc);
    __syncthreads();
    float acc2 = b2[f];
#pragma unroll 8
    for (int k = 0; k < FDIM; k++) acc2 = fmaf(trow[k], W2[k * FDIM + f], acc2);
    g_H[i * FDIM + f] += acc2;
}

// out[i] = ssp(h @ out_W1 + out_b1) @ out_W2 + out_b2
__global__ void out_kernel(const float* __restrict__ W1, const float* __restrict__ b1,
                           const float* __restrict__ W2, const float* __restrict__ b2,
                           float* __restrict__ out) {
    int i = blockIdx.x;
    int m = threadIdx.x;  // 32 threads
    const float* hrow = g_H + i * FDIM;
    float acc = b1[m];
#pragma unroll 8
    for (int k = 0; k < FDIM; k++) acc = fmaf(hrow[k], W1[k * 32 + m], acc);
    float u = sspf(acc) * W2[m];
#pragma unroll
    for (int off = 16; off > 0; off >>= 1)
        u += __shfl_down_sync(0xffffffffu, u, off);
    if (m == 0) out[i] = u + b2[0];
}

// ---------------------------------------------------------------------------
extern "C" void kernel_launch(void* const* d_in, const int* in_sizes, int n_in,
                              void* d_out, int out_size) {
    const int*   x      = (const int*)d_in[0];
    const float* r      = (const float*)d_in[1];
    const float* emb    = (const float*)d_in[2];
    const float* aw_W   = (const float*)d_in[3];
    const float* aw_b   = (const float*)d_in[4];
    const float* cf_W1  = (const float*)d_in[5];
    const float* cf_b1  = (const float*)d_in[6];
    const float* cf_W2  = (const float*)d_in[7];
    const float* cf_b2  = (const float*)d_in[8];
    const float* n_W1   = (const float*)d_in[9];
    const float* n_b1   = (const float*)d_in[10];
    const float* n_W2   = (const float*)d_in[11];
    const float* n_b2   = (const float*)d_in[12];
    const float* out_W1 = (const float*)d_in[13];
    const float* out_b1 = (const float*)d_in[14];
    const float* out_W2 = (const float*)d_in[15];
    const float* out_b2 = (const float*)d_in[16];
    float* out = (float*)d_out;

    size_t conv_smem = (size_t)(FDIM * SPAD + 16 * FDIM + 3 * FDIM) * sizeof(float);
    cudaFuncSetAttribute(conv_kernel, cudaFuncAttributeMaxDynamicSharedMemorySize,
                         (int)conv_smem);

    dist_kernel<<<N_ATOMS, 128>>>(r);
    table_kernel<<<dim3(NG, NLAYER), 128>>>(cf_W1);
    embed_kernel<<<N_ATOMS, 128>>>(x, emb);

    for (int l = 0; l < NLAYER; l++) {
        atomwise_kernel<<<N_ATOMS, 128>>>(aw_W + l * FDIM * FDIM, aw_b + l * FDIM);
        conv_kernel<<<N_ATOMS, CTHREADS, conv_smem>>>(
            l, cf_W2 + l * FDIM * FDIM, cf_b1 + l * FDIM, cf_b2 + l * FDIM);
        norm_kernel<<<N_ATOMS, 128>>>(n_W1 + l * FDIM * FDIM, n_b1 + l * FDIM,
                                      n_W2 + l * FDIM * FDIM, n_b2 + l * FDIM);
    }
    out_kernel<<<N_ATOMS, 32>>>(out_W1, out_b1, out_W2, out_b2, out);
}

// round 5
// speedup vs baseline: 3.4091x; 3.4091x over previous
#include <cuda_runtime.h>

#define N_ATOMS 512
#define FDIM    128
#define NKER    301
#define NLAYER  3
#define H_STEP  0.05f
#define INV_H   20.0f
#define NG      352
#define LN2     0.69314718056f

// ---- persistent device scratch (no runtime allocation) ----
__device__ float g_D[N_ATOMS * N_ATOMS];          // pairwise distances
__device__ float g_TAB[NLAYER * NG * FDIM];       // e@W1 table (stage 1)
__device__ float g_WTAB[NLAYER * NG * FDIM];      // final filter table (stage 2)
__device__ float g_H[N_ATOMS * FDIM];             // node features
__device__ float g_O[N_ATOMS * FDIM];             // atomwise output
__device__ float g_CP[N_ATOMS * FDIM];            // conv output (pre-norm)

__device__ __forceinline__ float sspf(float v) {
    float e = __expf(-fabsf(v));
    return fmaxf(v, 0.0f) + __logf(1.0f + e) - LN2;
}

// ---------------------------------------------------------------------------
// pairwise distances
// ---------------------------------------------------------------------------
__global__ void dist_kernel(const float* __restrict__ r) {
    int i = blockIdx.x;
    float rx = r[i * 3 + 0], ry = r[i * 3 + 1], rz = r[i * 3 + 2];
    for (int j = threadIdx.x; j < N_ATOMS; j += blockDim.x) {
        float dx = rx - r[j * 3 + 0];
        float dy = ry - r[j * 3 + 1];
        float dz = rz - r[j * 3 + 2];
        g_D[i * N_ATOMS + j] = sqrtf(dx * dx + dy * dy + dz * dz);
    }
}

// ---------------------------------------------------------------------------
// stage 1: TAB[l][g][f] = sum_k exp(-10*(t_g - 0.1k)^2) * cf_W1[l][k][f]
// t_g = (g-1)*H_STEP
// ---------------------------------------------------------------------------
__global__ void table_kernel(const float* __restrict__ cf_W1) {
    int g = blockIdx.x;
    int l = blockIdx.y;
    float t = (g - 1) * H_STEP;
    __shared__ float e_sm[NKER];
    for (int k = threadIdx.x; k < NKER; k += blockDim.x) {
        float u = t - 0.1f * (float)k;
        e_sm[k] = expf(-10.0f * u * u);
    }
    __syncthreads();
    int f = threadIdx.x;
    const float* W = cf_W1 + l * NKER * FDIM + f;
    float acc = 0.0f;
    for (int k = 0; k < NKER; k++)
        acc = fmaf(e_sm[k], W[k * FDIM], acc);
    g_TAB[(l * NG + g) * FDIM + f] = acc;
}

// ---------------------------------------------------------------------------
// stage 2: WTAB[l][g][f] = ssp( ssp(TAB[l][g]+b1[l]) @ W2[l] + b2[l] )[f]
// ---------------------------------------------------------------------------
__global__ void wtab_kernel(const float* __restrict__ cf_b1,
                            const float* __restrict__ cf_W2,
                            const float* __restrict__ cf_b2) {
    int g = blockIdx.x, l = blockIdx.y, f = threadIdx.x;
    __shared__ float row[FDIM];
    row[f] = sspf(g_TAB[(l * NG + g) * FDIM + f] + cf_b1[l * FDIM + f]);
    __syncthreads();
    const float* W2 = cf_W2 + l * FDIM * FDIM + f;
    float acc = cf_b2[l * FDIM + f];
#pragma unroll 8
    for (int k = 0; k < FDIM; k++)
        acc = fmaf(row[k], W2[k * FDIM], acc);
    g_WTAB[(l * NG + g) * FDIM + f] = sspf(acc);
}

// ---------------------------------------------------------------------------
__global__ void embed_kernel(const int* __restrict__ x, const float* __restrict__ emb) {
    g_H[blockIdx.x * FDIM + threadIdx.x] = emb[x[blockIdx.x] * FDIM + threadIdx.x];
}

// ---------------------------------------------------------------------------
// o = h @ W + b  — 4 atoms per block for latency hiding + W reuse
// ---------------------------------------------------------------------------
#define AW_ATOMS 4
__global__ void atomwise_kernel(const float* __restrict__ W, const float* __restrict__ b) {
    int a0 = blockIdx.x * AW_ATOMS;
    int f = threadIdx.x;
    __shared__ float hsm[AW_ATOMS][FDIM];
#pragma unroll
    for (int a = 0; a < AW_ATOMS; a++) hsm[a][f] = g_H[(a0 + a) * FDIM + f];
    __syncthreads();
    float acc[AW_ATOMS];
    float bf = b[f];
#pragma unroll
    for (int a = 0; a < AW_ATOMS; a++) acc[a] = bf;
#pragma unroll 4
    for (int k = 0; k < FDIM; k++) {
        float wv = W[k * FDIM + f];
#pragma unroll
        for (int a = 0; a < AW_ATOMS; a++)
            acc[a] = fmaf(hsm[a][k], wv, acc[a]);
    }
#pragma unroll
    for (int a = 0; a < AW_ATOMS; a++) g_O[(a0 + a) * FDIM + f] = acc[a];
}

// ---------------------------------------------------------------------------
// conv: cpre[i,f] = sum_j o[j,f] * catmull_rom(WTAB, d_ij)[f]
// 128 CTAs x 4 atoms; WTAB layer slice staged in smem (180KB)
// 256 threads: fp = tid&63 owns features {2fp, 2fp+1}; jg = tid>>6 strides j by 4
// ---------------------------------------------------------------------------
#define CONV_ATOMS 4
__global__ void __launch_bounds__(256, 1)
conv_kernel(int l) {
    extern __shared__ float sm[];
    float*  WT  = sm;                       // [NG*FDIM]
    float*  dsm = WT + NG * FDIM;           // [512]
    float2* red = (float2*)(dsm + N_ATOMS); // [4][64]

    const int tid = threadIdx.x;
    const int fp  = tid & 63;
    const int jg  = tid >> 6;

    // stage table into smem (coalesced float4)
    {
        const float4* src = (const float4*)(g_WTAB + l * NG * FDIM);
        float4* dst = (float4*)WT;
#pragma unroll
        for (int it = 0; it < (NG * FDIM / 4) / 256; it++)
            dst[tid + it * 256] = src[tid + it * 256];
    }

    for (int ai = 0; ai < CONV_ATOMS; ai++) {
        int i = blockIdx.x * CONV_ATOMS + ai;
        __syncthreads();
        for (int j = tid; j < N_ATOMS; j += 256) dsm[j] = g_D[i * N_ATOMS + j];
        __syncthreads();

        float2 acc = make_float2(0.0f, 0.0f);
#pragma unroll 2
        for (int j = jg; j < N_ATOMS; j += 4) {
            float d  = dsm[j];
            float a  = fminf(d * INV_H, 347.5f);
            int   gi = (int)a;              // a >= 0 -> trunc == floor
            float x  = a - (float)gi;
            float x2 = x * x, x3 = x2 * x;
            float cw0 = 0.5f * (-x3 + 2.0f * x2 - x);
            float cw1 = 0.5f * (3.0f * x3 - 5.0f * x2 + 2.0f);
            float cw2 = 0.5f * (-3.0f * x3 + 4.0f * x2 + x);
            float cw3 = 0.5f * (x3 - x2);
            const float* T = WT + gi * FDIM + 2 * fp;
            float2 T0 = *(const float2*)(T);
            float2 T1 = *(const float2*)(T + FDIM);
            float2 T2 = *(const float2*)(T + 2 * FDIM);
            float2 T3 = *(const float2*)(T + 3 * FDIM);
            float wx = fmaf(cw0, T0.x, fmaf(cw1, T1.x, fmaf(cw2, T2.x, cw3 * T3.x)));
            float wy = fmaf(cw0, T0.y, fmaf(cw1, T1.y, fmaf(cw2, T2.y, cw3 * T3.y)));
            float2 o2 = *(const float2*)(g_O + j * FDIM + 2 * fp);
            acc.x = fmaf(o2.x, wx, acc.x);
            acc.y = fmaf(o2.y, wy, acc.y);
        }

        red[jg * 64 + fp] = acc;
        __syncthreads();
        if (tid < 64) {
            float2 s0 = red[fp], s1 = red[64 + fp], s2 = red[128 + fp], s3 = red[192 + fp];
            float2 s = make_float2(s0.x + s1.x + s2.x + s3.x,
                                   s0.y + s1.y + s2.y + s3.y);
            *(float2*)(g_CP + i * FDIM + 2 * fp) = s;
        }
    }
}

// ---------------------------------------------------------------------------
// h += ssp(cpre @ n_W1 + n_b1) @ n_W2 + n_b2  — 4 atoms per block
// ---------------------------------------------------------------------------
__global__ void norm_kernel(const float* __restrict__ W1, const float* __restrict__ b1,
                            const float* __restrict__ W2, const float* __restrict__ b2) {
    int a0 = blockIdx.x * AW_ATOMS;
    int f = threadIdx.x;
    __shared__ float csm[AW_ATOMS][FDIM];
    __shared__ float tsm[AW_ATOMS][FDIM];
#pragma unroll
    for (int a = 0; a < AW_ATOMS; a++) csm[a][f] = g_CP[(a0 + a) * FDIM + f];
    __syncthreads();
    float acc[AW_ATOMS];
    float bf = b1[f];
#pragma unroll
    for (int a = 0; a < AW_ATOMS; a++) acc[a] = bf;
#pragma unroll 4
    for (int k = 0; k < FDIM; k++) {
        float wv = W1[k * FDIM + f];
#pragma unroll
        for (int a = 0; a < AW_ATOMS; a++)
            acc[a] = fmaf(csm[a][k], wv, acc[a]);
    }
#pragma unroll
    for (int a = 0; a < AW_ATOMS; a++) tsm[a][f] = sspf(acc[a]);
    __syncthreads();
    float bf2 = b2[f];
#pragma unroll
    for (int a = 0; a < AW_ATOMS; a++) acc[a] = bf2;
#pragma unroll 4
    for (int k = 0; k < FDIM; k++) {
        float wv = W2[k * FDIM + f];
#pragma unroll
        for (int a = 0; a < AW_ATOMS; a++)
            acc[a] = fmaf(tsm[a][k], wv, acc[a]);
    }
#pragma unroll
    for (int a = 0; a < AW_ATOMS; a++) g_H[(a0 + a) * FDIM + f] += acc[a];
}

// ---------------------------------------------------------------------------
__global__ void out_kernel(const float* __restrict__ W1, const float* __restrict__ b1,
                           const float* __restrict__ W2, const float* __restrict__ b2,
                           float* __restrict__ out) {
    int i = blockIdx.x;
    int m = threadIdx.x;  // 32 threads
    const float* hrow = g_H + i * FDIM;
    float acc = b1[m];
#pragma unroll 8
    for (int k = 0; k < FDIM; k++) acc = fmaf(hrow[k], W1[k * 32 + m], acc);
    float u = sspf(acc) * W2[m];
#pragma unroll
    for (int off = 16; off > 0; off >>= 1)
        u += __shfl_down_sync(0xffffffffu, u, off);
    if (m == 0) out[i] = u + b2[0];
}

// ---------------------------------------------------------------------------
extern "C" void kernel_launch(void* const* d_in, const int* in_sizes, int n_in,
                              void* d_out, int out_size) {
    const int*   x      = (const int*)d_in[0];
    const float* r      = (const float*)d_in[1];
    const float* emb    = (const float*)d_in[2];
    const float* aw_W   = (const float*)d_in[3];
    const float* aw_b   = (const float*)d_in[4];
    const float* cf_W1  = (const float*)d_in[5];
    const float* cf_b1  = (const float*)d_in[6];
    const float* cf_W2  = (const float*)d_in[7];
    const float* cf_b2  = (const float*)d_in[8];
    const float* n_W1   = (const float*)d_in[9];
    const float* n_b1   = (const float*)d_in[10];
    const float* n_W2   = (const float*)d_in[11];
    const float* n_b2   = (const float*)d_in[12];
    const float* out_W1 = (const float*)d_in[13];
    const float* out_b1 = (const float*)d_in[14];
    const float* out_W2 = (const float*)d_in[15];
    const float* out_b2 = (const float*)d_in[16];
    float* out = (float*)d_out;

    size_t conv_smem = (size_t)(NG * FDIM + N_ATOMS) * sizeof(float)
                     + (size_t)(4 * 64) * sizeof(float2);
    cudaFuncSetAttribute(conv_kernel, cudaFuncAttributeMaxDynamicSharedMemorySize,
                         (int)conv_smem);

    dist_kernel<<<N_ATOMS, 128>>>(r);
    table_kernel<<<dim3(NG, NLAYER), 128>>>(cf_W1);
    wtab_kernel<<<dim3(NG, NLAYER), 128>>>(cf_b1, cf_W2, cf_b2);
    embed_kernel<<<N_ATOMS, 128>>>(x, emb);

    for (int l = 0; l < NLAYER; l++) {
        atomwise_kernel<<<N_ATOMS / AW_ATOMS, 128>>>(aw_W + l * FDIM * FDIM,
                                                     aw_b + l * FDIM);
        conv_kernel<<<N_ATOMS / CONV_ATOMS, 256, conv_smem>>>(l);
        norm_kernel<<<N_ATOMS / AW_ATOMS, 128>>>(n_W1 + l * FDIM * FDIM, n_b1 + l * FDIM,
                                                 n_W2 + l * FDIM * FDIM, n_b2 + l * FDIM);
    }
    out_kernel<<<N_ATOMS, 32>>>(out_W1, out_b1, out_W2, out_b2, out);
}

// round 7
// speedup vs baseline: 6.5969x; 1.9351x over previous
#include <cuda_runtime.h>
#include <cuda_fp16.h>

#define GRID    128
#define NTH     256
#define N_ATOMS 512
#define FDIM    128
#define NKER    301
#define NLAYER  3
#define NG      352
#define INV_H   20.0f
#define LN2     0.69314718056f

// ---- persistent device scratch (no runtime allocation) ----
__device__ float  g_D[N_ATOMS * N_ATOMS];
__device__ __half g_WTABh[NLAYER * NG * FDIM];
__device__ float  g_O[N_ATOMS * FDIM];
__device__ unsigned g_bar_cnt;
__device__ unsigned g_bar_gen;

// ---- shared memory layout (bytes) ----
#define SM_WT    0                               // fp16 table slice: NG*FDIM*2 = 90112
#define SM_CW    (NG * FDIM * 2)                 // float4[4][512] cw      -> +32768
#define SM_OFF   (SM_CW + 4 * 512 * 16)          // int[4][512] offsets    -> +8192
#define SM_RED   (SM_OFF + 4 * 512 * 4)          // float[8][4][128] red   -> +16384
#define SM_DSM   (SM_RED + 8 * 4 * 128 * 4)      // float[4][512] dists    -> +8192
#define SM_HSM   (SM_DSM + 4 * 512 * 4)          // float[4][128] h (persistent)
#define SM_CPS   (SM_HSM + 4 * 128 * 4)          // float[4][128] cpre (persistent)
#define SM_TOTAL (SM_CPS + 4 * 128 * 4)          // = 159744

__device__ __forceinline__ float sspf(float v) {
    float e = __expf(-fabsf(v));
    return fmaxf(v, 0.0f) + __logf(1.0f + e) - LN2;
}

// sense-free grid barrier: count + monotonically increasing generation.
// All CTAs read gen0 before the first arrival, so per-launch targets are safe.
__device__ __forceinline__ void gbar(unsigned target) {
    __syncthreads();
    if (threadIdx.x == 0) {
        __threadfence();                          // publish our writes to L2
        unsigned prev = atomicAdd(&g_bar_cnt, 1u);
        if (prev == GRID - 1) {
            g_bar_cnt = 0u;
            __threadfence();
            atomicAdd(&g_bar_gen, 1u);
        } else {
            while (*(volatile unsigned*)&g_bar_gen != target) __nanosleep(128);
        }
    }
    __syncthreads();
    __threadfence();                              // invalidate L1 before cross-CTA reads
}

// -------- inline phase helpers --------
__device__ __forceinline__ void atomwise_phase(const float* __restrict__ W,
                                               const float* __restrict__ b,
                                               const float* hsm, int i0, int tid) {
    int f = tid & 127, ah = tid >> 7;
    float bf = b[f];
    float a0 = bf, a1 = bf;
#pragma unroll 8
    for (int k = 0; k < FDIM; k++) {
        float w = W[k * FDIM + f];
        a0 = fmaf(hsm[ah * FDIM + k], w, a0);
        a1 = fmaf(hsm[(ah + 2) * FDIM + k], w, a1);
    }
    g_O[(i0 + ah) * FDIM + f] = a0;
    g_O[(i0 + ah + 2) * FDIM + f] = a1;
}

__device__ __forceinline__ void norm_phase(const float* __restrict__ W1,
                                           const float* __restrict__ b1,
                                           const float* __restrict__ W2,
                                           const float* __restrict__ b2,
                                           const float* cps, float* hsm,
                                           float* tsm, int tid) {
    int f = tid & 127, ah = tid >> 7;
    float a0 = b1[f], a1 = b1[f];
#pragma unroll 8
    for (int k = 0; k < FDIM; k++) {
        float w = W1[k * FDIM + f];
        a0 = fmaf(cps[ah * FDIM + k], w, a0);
        a1 = fmaf(cps[(ah + 2) * FDIM + k], w, a1);
    }
    tsm[ah * FDIM + f] = sspf(a0);
    tsm[(ah + 2) * FDIM + f] = sspf(a1);
    __syncthreads();
    a0 = b2[f]; a1 = b2[f];
#pragma unroll 8
    for (int k = 0; k < FDIM; k++) {
        float w = W2[k * FDIM + f];
        a0 = fmaf(tsm[ah * FDIM + k], w, a0);
        a1 = fmaf(tsm[(ah + 2) * FDIM + k], w, a1);
    }
    hsm[ah * FDIM + f] += a0;
    hsm[(ah + 2) * FDIM + f] += a1;
}

// ---------------------------------------------------------------------------
__global__ void __launch_bounds__(NTH, 1)
schnet_fused(const int* __restrict__ x, const float* __restrict__ r,
             const float* __restrict__ emb,
             const float* __restrict__ aw_W, const float* __restrict__ aw_b,
             const float* __restrict__ cf_W1, const float* __restrict__ cf_b1,
             const float* __restrict__ cf_W2, const float* __restrict__ cf_b2,
             const float* __restrict__ n_W1, const float* __restrict__ n_b1,
             const float* __restrict__ n_W2, const float* __restrict__ n_b2,
             const float* __restrict__ out_W1, const float* __restrict__ out_b1,
             const float* __restrict__ out_W2, const float* __restrict__ out_b2,
             float* __restrict__ out)
{
    extern __shared__ char sm[];
    float* hsm = (float*)(sm + SM_HSM);
    float* cps = (float*)(sm + SM_CPS);
    const int tid = threadIdx.x;
    const int i0  = blockIdx.x * 4;

    unsigned gen0 = (tid == 0) ? *(volatile unsigned*)&g_bar_gen : 0u;
    unsigned nbar = 0;

    // ==================== Phase A: dist + embed + aw0 + tables ====================
    // pairwise distances for own 4 rows
#pragma unroll
    for (int a = 0; a < 4; a++) {
        int i = i0 + a;
        float rx = r[i * 3], ry = r[i * 3 + 1], rz = r[i * 3 + 2];
        for (int j = tid; j < N_ATOMS; j += NTH) {
            float dx = rx - r[j * 3], dy = ry - r[j * 3 + 1], dz = rz - r[j * 3 + 2];
            g_D[i * N_ATOMS + j] = sqrtf(dx * dx + dy * dy + dz * dz);
        }
    }
    // embed own atoms into persistent smem h
    {
        int f = tid & 127, ah = tid >> 7;
        hsm[ah * FDIM + f]       = emb[x[i0 + ah] * FDIM + f];
        hsm[(ah + 2) * FDIM + f] = emb[x[i0 + ah + 2] * FDIM + f];
    }
    __syncthreads();
    atomwise_phase(aw_W, aw_b, hsm, i0, tid);

    // truncated-RBF table + filter MLP -> fp16 WTAB
    {
        float* esm = (float*)(sm + SM_WT);       // [8][40]
        float* ssm = esm + 8 * 40;               // [8][128]
        for (int u = blockIdx.x; u < 132; u += GRID) {
            int l = u / 44, g0 = (u % 44) * 8;
            float t0 = (g0 - 1) * 0.05f;
            int kmin = (int)ceilf((t0 - 1.6f) * 10.0f);            if (kmin < 0) kmin = 0;
            int kmax = (int)floorf((t0 + 0.35f + 1.6f) * 10.0f);   if (kmax > NKER - 1) kmax = NKER - 1;
            int nk = kmax - kmin + 1;
            __syncthreads();
            for (int idx = tid; idx < 8 * 40; idx += NTH) {
                int rr = idx / 40, kk = idx % 40;
                float e = 0.0f;
                if (kk < nk) {
                    float uu = (g0 + rr - 1) * 0.05f - 0.1f * (float)(kmin + kk);
                    e = __expf(-10.0f * uu * uu);
                }
                esm[rr * 40 + kk] = e;
            }
            __syncthreads();
            {
                int f = tid & 127, rh = tid >> 7;
                const float* W1 = cf_W1 + l * NKER * FDIM;
                float b1f = cf_b1[l * FDIM + f];
                for (int rr = rh; rr < 8; rr += 2) {
                    float acc = 0.0f;
                    for (int kk = 0; kk < nk; kk++)
                        acc = fmaf(esm[rr * 40 + kk], W1[(kmin + kk) * FDIM + f], acc);
                    ssm[rr * FDIM + f] = sspf(acc + b1f);
                }
            }
            __syncthreads();
            {
                int f = tid & 127, rh = tid >> 7;
                const float* W2 = cf_W2 + l * FDIM * FDIM;
                float b2f = cf_b2[l * FDIM + f];
                float acc[4];
#pragma unroll
                for (int q = 0; q < 4; q++) acc[q] = b2f;
#pragma unroll 2
                for (int k = 0; k < FDIM; k++) {
                    float w = W2[k * FDIM + f];
#pragma unroll
                    for (int q = 0; q < 4; q++)
                        acc[q] = fmaf(ssm[(rh * 4 + q) * FDIM + k], w, acc[q]);
                }
#pragma unroll
                for (int q = 0; q < 4; q++)
                    g_WTABh[(l * NG + g0 + rh * 4 + q) * FDIM + f] = __float2half_rn(sspf(acc[q]));
            }
        }
    }
    gbar(gen0 + (++nbar));   // B1: o + WTAB published

    // ==================== layer loop ====================
    for (int l = 0; l < NLAYER; l++) {
        // ---- conv: cpre[a,f] = sum_j o[j,f] * CR-interp(WTAB_l, d_aj)[f] ----
        {
            // stage fp16 table slice
            uint4* dst = (uint4*)(sm + SM_WT);
            const uint4* src = (const uint4*)(g_WTABh + l * NG * FDIM);
#pragma unroll
            for (int it = 0; it < (NG * FDIM * 2 / 16) / NTH; it++)
                dst[tid + it * NTH] = src[tid + it * NTH];
            // load own distance rows
            float* dsm = (float*)(sm + SM_DSM);
#pragma unroll
            for (int a = 0; a < 4; a++)
                for (int j = tid; j < N_ATOMS; j += NTH)
                    dsm[a * 512 + j] = g_D[(i0 + a) * N_ATOMS + j];
            __syncthreads();
            // precompute Catmull-Rom weights + row byte offsets (per atom, per j)
            float4* cw4 = (float4*)(sm + SM_CW);
            int*    offs = (int*)(sm + SM_OFF);
            for (int idx = tid; idx < 4 * 512; idx += NTH) {
                float d  = dsm[idx];
                float aa = fminf(d * INV_H, 347.5f);
                int   gi = (int)aa;
                float xx = aa - (float)gi;
                float x2 = xx * xx, x3 = x2 * xx;
                cw4[idx] = make_float4(0.5f * (-x3 + 2.0f * x2 - xx),
                                       0.5f * (3.0f * x3 - 5.0f * x2 + 2.0f),
                                       0.5f * (-3.0f * x3 + 4.0f * x2 + xx),
                                       0.5f * (x3 - x2));
                offs[idx] = gi * (FDIM * 2);
            }
            __syncthreads();

            const int fp = tid & 31, jg = tid >> 5;
            float acc[4][4];
#pragma unroll
            for (int a = 0; a < 4; a++)
#pragma unroll
                for (int c = 0; c < 4; c++) acc[a][c] = 0.0f;
            const char* WTb = sm + SM_WT;

            for (int j = jg; j < N_ATOMS; j += 8) {
                float w[4][4];
#pragma unroll
                for (int a = 0; a < 4; a++) {
                    float4 cw = cw4[a * 512 + j];
                    int off   = offs[a * 512 + j];
                    const char* T = WTb + off + fp * 8;
                    uint2 q0 = *(const uint2*)(T);
                    uint2 q1 = *(const uint2*)(T + 256);
                    uint2 q2 = *(const uint2*)(T + 512);
                    uint2 q3 = *(const uint2*)(T + 768);
                    float2 p0  = __half22float2(*(__half2*)&q0.x);
                    float2 p0b = __half22float2(*(__half2*)&q0.y);
                    float2 p1  = __half22float2(*(__half2*)&q1.x);
                    float2 p1b = __half22float2(*(__half2*)&q1.y);
                    float2 p2  = __half22float2(*(__half2*)&q2.x);
                    float2 p2b = __half22float2(*(__half2*)&q2.y);
                    float2 p3  = __half22float2(*(__half2*)&q3.x);
                    float2 p3b = __half22float2(*(__half2*)&q3.y);
                    w[a][0] = fmaf(cw.x, p0.x,  fmaf(cw.y, p1.x,  fmaf(cw.z, p2.x,  cw.w * p3.x)));
                    w[a][1] = fmaf(cw.x, p0.y,  fmaf(cw.y, p1.y,  fmaf(cw.z, p2.y,  cw.w * p3.y)));
                    w[a][2] = fmaf(cw.x, p0b.x, fmaf(cw.y, p1b.x, fmaf(cw.z, p2b.x, cw.w * p3b.x)));
                    w[a][3] = fmaf(cw.x, p0b.y, fmaf(cw.y, p1b.y, fmaf(cw.z, p2b.y, cw.w * p3b.y)));
                }
                float4 ov = *(const float4*)(g_O + j * FDIM + fp * 4);
#pragma unroll
                for (int a = 0; a < 4; a++) {
                    acc[a][0] = fmaf(ov.x, w[a][0], acc[a][0]);
                    acc[a][1] = fmaf(ov.y, w[a][1], acc[a][1]);
                    acc[a][2] = fmaf(ov.z, w[a][2], acc[a][2]);
                    acc[a][3] = fmaf(ov.w, w[a][3], acc[a][3]);
                }
            }
            float* red = (float*)(sm + SM_RED);   // [8][4][128]
#pragma unroll
            for (int a = 0; a < 4; a++)
                *(float4*)(red + (jg * 4 + a) * FDIM + fp * 4) =
                    make_float4(acc[a][0], acc[a][1], acc[a][2], acc[a][3]);
            __syncthreads();
            for (int idx = tid; idx < 512; idx += NTH) {
                int a = idx >> 7, f = idx & 127;
                float s = 0.0f;
#pragma unroll
                for (int g = 0; g < 8; g++) s += red[(g * 4 + a) * FDIM + f];
                cps[a * FDIM + f] = s;
            }
            __syncthreads();
        }

        if (l < NLAYER - 1) {
            gbar(gen0 + (++nbar));   // all conv reads of o done -> safe to overwrite
            norm_phase(n_W1 + l * FDIM * FDIM, n_b1 + l * FDIM,
                       n_W2 + l * FDIM * FDIM, n_b2 + l * FDIM,
                       cps, hsm, (float*)(sm + SM_WT), tid);
            __syncthreads();
            atomwise_phase(aw_W + (l + 1) * FDIM * FDIM, aw_b + (l + 1) * FDIM,
                           hsm, i0, tid);
            gbar(gen0 + (++nbar));   // new o published
        }
    }

    // ---- final norm + output head (all CTA-local) ----
    norm_phase(n_W1 + 2 * FDIM * FDIM, n_b1 + 2 * FDIM,
               n_W2 + 2 * FDIM * FDIM, n_b2 + 2 * FDIM,
               cps, hsm, (float*)(sm + SM_WT), tid);
    __syncthreads();
    {
        int wid = tid >> 5, lane = tid & 31;
        if (wid < 4) {
            const float* hrow = hsm + wid * FDIM;
            float acc = out_b1[lane];
#pragma unroll 8
            for (int k = 0; k < FDIM; k++)
                acc = fmaf(hrow[k], out_W1[k * 32 + lane], acc);
            float u = sspf(acc) * out_W2[lane];
#pragma unroll
            for (int off = 16; off > 0; off >>= 1)
                u += __shfl_down_sync(0xffffffffu, u, off);
            if (lane == 0) out[i0 + wid] = u + out_b2[0];
        }
    }
}

// ---------------------------------------------------------------------------
extern "C" void kernel_launch(void* const* d_in, const int* in_sizes, int n_in,
                              void* d_out, int out_size) {
    const int*   x      = (const int*)d_in[0];
    const float* r      = (const float*)d_in[1];
    const float* emb    = (const float*)d_in[2];
    const float* aw_W   = (const float*)d_in[3];
    const float* aw_b   = (const float*)d_in[4];
    const float* cf_W1  = (const float*)d_in[5];
    const float* cf_b1  = (const float*)d_in[6];
    const float* cf_W2  = (const float*)d_in[7];
    const float* cf_b2  = (const float*)d_in[8];
    const float* n_W1   = (const float*)d_in[9];
    const float* n_b1   = (const float*)d_in[10];
    const float* n_W2   = (const float*)d_in[11];
    const float* n_b2   = (const float*)d_in[12];
    const float* out_W1 = (const float*)d_in[13];
    const float* out_b1 = (const float*)d_in[14];
    const float* out_W2 = (const float*)d_in[15];
    const float* out_b2 = (const float*)d_in[16];
    float* out = (float*)d_out;

    cudaFuncSetAttribute(schnet_fused, cudaFuncAttributeMaxDynamicSharedMemorySize,
                         SM_TOTAL);
    schnet_fused<<<GRID, NTH, SM_TOTAL>>>(
        x, r, emb, aw_W, aw_b, cf_W1, cf_b1, cf_W2, cf_b2,
        n_W1, n_b1, n_W2, n_b2, out_W1, out_b1, out_W2, out_b2, out);
}